// round 15
// baseline (speedup 1.0000x reference)
#include <cuda_runtime.h>
#include <cuda_fp16.h>
#include <math.h>

// ---------------- problem constants ----------------
#define HH      1024
#define WW      1024
#define NPIX    (HH * WW)
#define KK      8
#define WS      11
#define RAD     5

// ---------------- main tiling: 64 x 32 tiles, 512 threads, 2 blocks/SM ----------------
#define TW       64
#define TH       32
#define HTW      74            // TW + 2*RAD
#define HTH      42            // TH + 2*RAD
#define HT       (HTW * HTH)   // 3108
#define NT2      512
#define NLOAD    7             // ceil(HT / NT2)
#define VBW      75            // vb f01 row stride (float2 units)
#define VBW2     76            // vb f2h row stride (half units)
#define MAINB    512           // stats tiles
#define BLENDB   256           // blend blocks (2 tiles each)

// smem layout (bytes): fixed double buffers (no rotating pointers)
#define OFF_PA_F01   0                    // float2[HT]    24864
#define OFF_PB_F01   24864                // float2[HT]    24864
#define OFF_VBA_F01  49728                // float2[32*75] 19200
#define OFF_VBB_F01  68928                // float2[32*75] 19200
#define OFF_PA_F2    88128                // half[HT]       6216
#define OFF_PB_F2    94344                // half[HT]       6216
#define OFF_VBA_F2   100560               // half[32*76]    4864
#define OFF_VBB_F2   105424               // half[32*76]    4864
#define SMEM_TOTAL   110288

struct GW { float w[WS]; };

// ---------------- scratch (static device globals; no allocation) ----------------
__device__ uint2 g_muY2[KK * NPIX / 4];   // per-pixel muYs (shifted) as 4 halfs (16MB)
__device__ uint2 g_cs2[NPIX / 4];         // per-pixel cs_map as 4 halfs (2MB)
__device__ uint2 g_mx2[NPIX / 4];         // per-pixel muXs (shifted) as 4 halfs (2MB)
__device__ float g_lY_part[KK * MAINB];
__device__ float g_lG[KK];
__device__ float g_q_part[BLENDB];
__device__ int   g_done1 = 0;
__device__ int   g_done2 = 0;

// ======================= separable blur helpers =======================
// Vertical: 6 consecutive output rows per task, 16 taps; 444 tasks / 512 thr.
__device__ __forceinline__ void vpass6(const float2* __restrict__ f01,
                                       const __half* __restrict__ f2h,
                                       float2* __restrict__ vb01,
                                       __half* __restrict__ vb2h,
                                       const float* gw, int tid) {
    if (tid < 444) {
        int g = tid / HTW, c = tid - g * HTW;
        int r0 = g * 6;
        float ax[6], ay[6], az[6];
#pragma unroll
        for (int i = 0; i < 6; i++) { ax[i] = 0.f; ay[i] = 0.f; az[i] = 0.f; }
        const float2* p01 = f01 + r0 * HTW + c;
        const __half* p2  = f2h + r0 * HTW + c;
        if (r0 + 15 < HTH) {            // rowgroups 0-4: all taps in range
#pragma unroll
            for (int j = 0; j < 16; j++) {
                float2 v = p01[j * HTW];
                float  z = __half2float(p2[j * HTW]);
#pragma unroll
                for (int i = 0; i < 6; i++) {
                    if (i <= j && j - i <= 10) {
                        float gg = gw[j - i];
                        ax[i] += gg * v.x; ay[i] += gg * v.y; az[i] += gg * z;
                    }
                }
            }
        } else {                         // last rowgroup: guard tail taps
#pragma unroll
            for (int j = 0; j < 16; j++) {
                if (r0 + j < HTH) {
                    float2 v = p01[j * HTW];
                    float  z = __half2float(p2[j * HTW]);
#pragma unroll
                    for (int i = 0; i < 6; i++) {
                        if (i <= j && j - i <= 10) {
                            float gg = gw[j - i];
                            ax[i] += gg * v.x; ay[i] += gg * v.y; az[i] += gg * z;
                        }
                    }
                }
            }
        }
#pragma unroll
        for (int i = 0; i < 6; i++) {
            int r = r0 + i;
            if (r < TH) {
                vb01[r * VBW + c] = make_float2(ax[i], ay[i]);
                vb2h[r * VBW2 + c] = __float2half_rn(az[i]);
            }
        }
    }
}

// Horizontal: lane = row (f01 stride conflict-free; f2h benign), 4 cols/thread.
__device__ __forceinline__ void hpass(const float2* __restrict__ vb01,
                                      const __half* __restrict__ vb2h,
                                      const float* gw, int row, int x0, float3* out) {
    float ax[4], ay[4], az[4];
#pragma unroll
    for (int i = 0; i < 4; i++) { ax[i] = 0.f; ay[i] = 0.f; az[i] = 0.f; }
    const float2* p01 = vb01 + row * VBW + x0;
    const __half* p2  = vb2h + row * VBW2 + x0;
#pragma unroll
    for (int j = 0; j < 14; j++) {
        float2 v = p01[j];
        float  z = __half2float(p2[j]);
#pragma unroll
        for (int i = 0; i < 4; i++) {
            if (i <= j && j - i <= 10) {
                float gg = gw[j - i];
                ax[i] += gg * v.x; ay[i] += gg * v.y; az[i] += gg * z;
            }
        }
    }
#pragma unroll
    for (int i = 0; i < 4; i++) out[i] = make_float3(ax[i], ay[i], az[i]);
}

// Pack-write: load bunch k tile (shifted), build (s, s²) fp32 + (s·o') half.
__device__ __forceinline__ void pack_write(const float* __restrict__ bb,
                                           const int* goff, const __half2* h01,
                                           const __half2* h2p,
                                           float2* __restrict__ s_f01,
                                           __half* __restrict__ s_f2h, int tid) {
#pragma unroll
    for (int i = 0; i < NLOAD; i++) {
        int e = tid + i * NT2;
        if (e < HT) {
            int o = goff[i];
            float v0 = -0.5f, v1 = -0.5f, v2 = -0.5f;
            if (o >= 0) {
                v0 = bb[o] - 0.5f; v1 = bb[NPIX + o] - 0.5f; v2 = bb[2 * NPIX + o] - 0.5f;
            }
            float2 o01 = __half22float2(h01[i]);
            float  o2  = __half2float((i & 1) ? __high2half(h2p[i >> 1])
                                              : __low2half(h2p[i >> 1]));
            s_f01[e] = make_float2((v0 + v1 + v2) * (1.f / 3.f),
                                   (v0 * v0 + v1 * v1 + v2 * v2) * (1.f / 3.f));
            s_f2h[e] = __float2half_rn((v0 * o01.x + v1 * o01.y + v2 * o2) * (1.f / 3.f));
        }
    }
}

__device__ __forceinline__ uint2 pack4h(float a, float b, float c, float d) {
    __half2 p0 = __floats2half2_rn(a, b);
    __half2 p1 = __floats2half2_rn(c, d);
    uint2 u;
    u.x = *(const unsigned int*)&p0;
    u.y = *(const unsigned int*)&p1;
    return u;
}

// per-exposure stats update (argmax, muY store, lY partial)
__device__ __forceinline__ void do_stats(int k, const float3* yo, const float* muXs,
                                         float* best, float* bestXY, int* pidx,
                                         float* s_ly, int T, int tid, int lane, int wid) {
#pragma unroll
    for (int i = 0; i < 4; i++) {
        float muYs = yo[i].x;
        float sY2 = yo[i].y - muYs * muYs;
        float sXY = yo[i].z - muXs[i] * muYs;
        if (sY2 > best[i]) { best[i] = sY2; bestXY[i] = sXY; pidx[i] = k; }
    }
    g_muY2[(size_t)(T * KK + k) * NT2 + tid] =
        pack4h(yo[0].x, yo[1].x, yo[2].x, yo[3].x);
    float lsum = yo[0].x + yo[1].x + yo[2].x + yo[3].x;
#pragma unroll
    for (int o = 16; o > 0; o >>= 1) lsum += __shfl_xor_sync(0xffffffffu, lsum, o);
    if (lane == 0) s_ly[wid * KK + k] = lsum;
}

// ======================= k1: stats pass (single barrier per interval) =======================
// Shifted domain v' = v - 0.5 (exact; reference zero-pads raw => padded v' = -0.5).
// Pipeline with FIXED buffers (no pointer registers):
//   interval j: pack(k_{j+1})->P_par ; vpass(P_other: pack k_j)->vb_w ; hpass(vb_r)->stats(k_{j-1}) ; sync
__global__ __launch_bounds__(NT2, 2) void mef_stats_k(
    const float* __restrict__ img,
    const float* __restrict__ bunch,
    float* __restrict__ patch_out,
    GW gwp)
{
    extern __shared__ char sm[];
    float2* PA01  = (float2*)(sm + OFF_PA_F01);
    float2* PB01  = (float2*)(sm + OFF_PB_F01);
    float2* vbA01 = (float2*)(sm + OFF_VBA_F01);
    float2* vbB01 = (float2*)(sm + OFF_VBB_F01);
    __half* PA2   = (__half*)(sm + OFF_PA_F2);
    __half* PB2   = (__half*)(sm + OFF_PB_F2);
    __half* vbA2  = (__half*)(sm + OFF_VBA_F2);
    __half* vbB2  = (__half*)(sm + OFF_VBB_F2);
    __shared__ float s_ly[16 * KK];
    __shared__ float qw[16];
    const float* gw = gwp.w;

    int tid = threadIdx.x;
    int lane = tid & 31;
    int wid = tid >> 5;
    int row = tid & 31;          // hpass: output row
    int x0c = (tid >> 5) * 4;    // hpass: 4 consecutive output cols
    int bx = blockIdx.x, by = blockIdx.y;
    int T  = by * gridDim.x + bx;
    int gx0 = bx * TW - RAD, gy0 = by * TH - RAD;

    // per-thread halo state
    int goff[NLOAD];
    __half2 h01[NLOAD];
    __half2 h2p[4];
#pragma unroll
    for (int i = 0; i < 4; i++) h2p[i] = __halves2half2(__float2half(0.f), __float2half(0.f));

    // ---- interval 0: X field -> PA ----
#pragma unroll
    for (int i = 0; i < NLOAD; i++) {
        int e = tid + i * NT2;
        float o0 = -0.5f, o1 = -0.5f, o2 = -0.5f;
        int o = -2;
        if (e < HT) {
            int hy = e / HTW, hx = e - hy * HTW;
            int gy = gy0 + hy, gx = gx0 + hx;
            o = (((unsigned)gy < HH) && ((unsigned)gx < WW)) ? gy * WW + gx : -1;
            if (o >= 0) {
                o0 = img[o] - 0.5f; o1 = img[NPIX + o] - 0.5f; o2 = img[2 * NPIX + o] - 0.5f;
            }
            PA01[e] = make_float2((o0 + o1 + o2) * (1.f / 3.f),
                                  (o0 * o0 + o1 * o1 + o2 * o2) * (1.f / 3.f));
            PA2[e] = __float2half_rn(0.f);
        }
        goff[i] = o;
        h01[i] = __floats2half2_rn(o0, o1);
        __half h2v = __float2half_rn(o2);
        if (i & 1) h2p[i >> 1] = __halves2half2(__low2half(h2p[i >> 1]), h2v);
        else       h2p[i >> 1] = __halves2half2(h2v, __high2half(h2p[i >> 1]));
    }
    __syncthreads();

    // ---- interval 1: vpass(PA:X)->vbA ; pack(k0)->PB ----
    pack_write(bunch, goff, h01, h2p, PB01, PB2, tid);
    vpass6(PA01, PA2, vbA01, vbA2, gw, tid);
    __syncthreads();

    float muXs[4], sX2[4];
    float best[4], bestXY[4];
    int pidx[4];
#pragma unroll
    for (int i = 0; i < 4; i++) { best[i] = -1e30f; bestXY[i] = 0.f; pidx[i] = 0; }

    // ---- interval 2 (j=0): hpass(vbA)->muX ; vpass(PB:k0)->vbB ; pack(k1)->PA ----
    {
        pack_write(bunch + (size_t)3 * NPIX, goff, h01, h2p, PA01, PA2, tid);
        vpass6(PB01, PB2, vbB01, vbB2, gw, tid);
        float3 xo[4];
        hpass(vbA01, vbA2, gw, row, x0c, xo);
#pragma unroll
        for (int i = 0; i < 4; i++) { muXs[i] = xo[i].x; sX2[i] = xo[i].y - muXs[i] * muXs[i]; }
        __syncthreads();
    }

    // ---- main loop: m = 0,1,2 ; handles stats k=2m, 2m+1 ; packs k=2m+2, 2m+3 ----
    for (int m = 0; m < 3; m++) {
        // j odd: hpass(vbB)->stats(2m) ; vpass(PA: k_{2m+1})->vbA ; pack(k_{2m+2})->PB
        {
            pack_write(bunch + (size_t)(3 * (2 * m + 2)) * NPIX, goff, h01, h2p, PB01, PB2, tid);
            vpass6(PA01, PA2, vbA01, vbA2, gw, tid);
            float3 yo[4];
            hpass(vbB01, vbB2, gw, row, x0c, yo);
            do_stats(2 * m, yo, muXs, best, bestXY, pidx, s_ly, T, tid, lane, wid);
            __syncthreads();
        }
        // j even: hpass(vbA)->stats(2m+1) ; vpass(PB: k_{2m+2})->vbB ; pack(k_{2m+3})->PA
        {
            pack_write(bunch + (size_t)(3 * (2 * m + 3)) * NPIX, goff, h01, h2p, PA01, PA2, tid);
            vpass6(PB01, PB2, vbB01, vbB2, gw, tid);
            float3 yo[4];
            hpass(vbA01, vbA2, gw, row, x0c, yo);
            do_stats(2 * m + 1, yo, muXs, best, bestXY, pidx, s_ly, T, tid, lane, wid);
            __syncthreads();
        }
    }

    // ---- j=7: hpass(vbB)->stats(k6) ; vpass(PA: k7)->vbA ----
    {
        vpass6(PA01, PA2, vbA01, vbA2, gw, tid);
        float3 yo[4];
        hpass(vbB01, vbB2, gw, row, x0c, yo);
        do_stats(6, yo, muXs, best, bestXY, pidx, s_ly, T, tid, lane, wid);
        __syncthreads();
    }
    // ---- j=8: hpass(vbA)->stats(k7) ----
    {
        float3 yo[4];
        hpass(vbA01, vbA2, gw, row, x0c, yo);
        do_stats(7, yo, muXs, best, bestXY, pidx, s_ly, T, tid, lane, wid);
    }
    __syncthreads();   // s_ly complete; vb buffers free

    // ---- epilogue ----
    if (tid < KK) {
        float v = 0.f;
#pragma unroll
        for (int w = 0; w < 16; w++) v += s_ly[w * KK + tid];
        g_lY_part[tid * MAINB + T] = v;
    }

    float* sidx = (float*)vbA01;   // staging: 2048 floats
    float csv[4];
#pragma unroll
    for (int i = 0; i < 4; i++) {
        csv[i] = (2.f * bestXY[i] + 9e-4f) /
                 fmaxf(sX2[i] + best[i] + 9e-4f, 1e-6f);   // C2 = 0.03^2
        sidx[row * 64 + x0c + i] = (float)pidx[i];
    }
    g_cs2[(size_t)T * NT2 + tid] = pack4h(csv[0], csv[1], csv[2], csv[3]);
    g_mx2[(size_t)T * NT2 + tid] = pack4h(muXs[0], muXs[1], muXs[2], muXs[3]);

    __syncthreads();
    if (patch_out) {
        // scalar stores: patch_out base is only 4B-aligned (out + 1).
        int px = tid * 4;
        int rr = px >> 6, cc = px & 63;
        float* dst = &patch_out[(by * TH + rr) * WW + bx * TW + cc];
        const float* src = &sidx[px];
        dst[0] = src[0]; dst[1] = src[1]; dst[2] = src[2]; dst[3] = src[3];
    }

    // ---- last block: fold lY partials -> lG ----
    __shared__ int isLast;
    if (tid == 0) {
        __threadfence();
        isLast = (atomicAdd(&g_done1, 1) == MAINB - 1);
    }
    __syncthreads();
    if (isLast) {
        __threadfence();
        for (int k = 0; k < KK; k++) {
            float s = g_lY_part[k * MAINB + tid];     // MAINB == NT2 == 512
#pragma unroll
            for (int o = 16; o > 0; o >>= 1) s += __shfl_xor_sync(0xffffffffu, s, o);
            if (lane == 0) qw[wid] = s;
            __syncthreads();
            if (tid < 16) {
                float v = qw[tid];
                v += __shfl_xor_sync(0x0000ffffu, v, 8);
                v += __shfl_xor_sync(0x0000ffffu, v, 4);
                v += __shfl_xor_sync(0x0000ffffu, v, 2);
                v += __shfl_xor_sync(0x0000ffffu, v, 1);
                if (tid == 0) {
                    double d = (double)v / (double)NPIX;   // = mean(muYs) = lY - 0.5
                    g_lG[k] = (float)exp(-(d * d) / 0.08); // DENOM_G = 2*0.2^2
                }
            }
            __syncthreads();
        }
        if (tid == 0) g_done1 = 0;   // self-reset for next graph replay
    }
}

// ======================= k2: luminance blend + q (2 tiles/block, 8 px/thread) =======================
__global__ __launch_bounds__(NT2) void mef_blend_k(float* __restrict__ q_out) {
    __shared__ float s_lG[KK];
    __shared__ float qw[16];
    int tid = threadIdx.x;
    int lane = tid & 31, wid = tid >> 5;
    int T  = blockIdx.x * 2 + (tid >> 8);
    int tp = tid & 255;               // uint4 index within tile

    if (tid < KK) s_lG[tid] = g_lG[tid];
    __syncthreads();

    const uint4* muY4 = (const uint4*)g_muY2;
    const uint4* cs4  = (const uint4*)g_cs2;
    const uint4* mx4  = (const uint4*)g_mx2;

    float num[8], den[8];
#pragma unroll
    for (int i = 0; i < 8; i++) { num[i] = 0.f; den[i] = 0.f; }

#pragma unroll
    for (int k = 0; k < KK; k++) {
        uint4 u = muY4[(size_t)(T * KK + k) * 256 + tp];
        float2 f0 = __half22float2(*(const __half2*)&u.x);
        float2 f1 = __half22float2(*(const __half2*)&u.y);
        float2 f2 = __half22float2(*(const __half2*)&u.z);
        float2 f3 = __half22float2(*(const __half2*)&u.w);
        float m[8] = {f0.x, f0.y, f1.x, f1.y, f2.x, f2.y, f3.x, f3.y};
        float lGk = s_lG[k];
#pragma unroll
        for (int i = 0; i < 8; i++) {
            float wgt = lGk * __expf(-(m[i] * m[i]) * (1.f / 0.08f));   // DENOM_L
            num[i] += wgt * (m[i] + 0.5f);
            den[i] += wgt;
        }
    }

    uint4 cu = cs4[(size_t)T * 256 + tp];
    uint4 mu = mx4[(size_t)T * 256 + tp];
    float cs[8], mx[8];
    {
        float2 a0 = __half22float2(*(const __half2*)&cu.x);
        float2 a1 = __half22float2(*(const __half2*)&cu.y);
        float2 a2 = __half22float2(*(const __half2*)&cu.z);
        float2 a3 = __half22float2(*(const __half2*)&cu.w);
        cs[0]=a0.x; cs[1]=a0.y; cs[2]=a1.x; cs[3]=a1.y;
        cs[4]=a2.x; cs[5]=a2.y; cs[6]=a3.x; cs[7]=a3.y;
        float2 b0 = __half22float2(*(const __half2*)&mu.x);
        float2 b1 = __half22float2(*(const __half2*)&mu.y);
        float2 b2 = __half22float2(*(const __half2*)&mu.z);
        float2 b3 = __half22float2(*(const __half2*)&mu.w);
        mx[0]=b0.x; mx[1]=b0.y; mx[2]=b1.x; mx[3]=b1.y;
        mx[4]=b2.x; mx[5]=b2.y; mx[6]=b3.x; mx[7]=b3.y;
    }

    float qsum = 0.f;
#pragma unroll
    for (int i = 0; i < 8; i++) {
        float muX  = mx[i] + 0.5f;
        float muYb = num[i] / den[i];
        float l = (2.f * muX * muYb + 1e-4f) /
                  fmaxf(muX * muX + muYb * muYb + 1e-4f, 1e-6f);   // C1 = 0.01^2
        qsum += l * cs[i];
    }

#pragma unroll
    for (int o = 16; o > 0; o >>= 1) qsum += __shfl_xor_sync(0xffffffffu, qsum, o);
    if (lane == 0) qw[wid] = qsum;
    __syncthreads();
    if (tid < 16) {
        float v = qw[tid];
        v += __shfl_xor_sync(0x0000ffffu, v, 8);
        v += __shfl_xor_sync(0x0000ffffu, v, 4);
        v += __shfl_xor_sync(0x0000ffffu, v, 2);
        v += __shfl_xor_sync(0x0000ffffu, v, 1);
        if (tid == 0) g_q_part[blockIdx.x] = v;
    }

    __shared__ int isLast;
    if (tid == 0) {
        __threadfence();
        isLast = (atomicAdd(&g_done2, 1) == BLENDB - 1);
    }
    __syncthreads();
    if (isLast) {
        __threadfence();
        float s = (tid < BLENDB) ? g_q_part[tid] : 0.f;
#pragma unroll
        for (int o = 16; o > 0; o >>= 1) s += __shfl_xor_sync(0xffffffffu, s, o);
        if (lane == 0) qw[wid] = s;
        __syncthreads();
        if (tid < 16) {
            float v = qw[tid];
            v += __shfl_xor_sync(0x0000ffffu, v, 8);
            v += __shfl_xor_sync(0x0000ffffu, v, 4);
            v += __shfl_xor_sync(0x0000ffffu, v, 2);
            v += __shfl_xor_sync(0x0000ffffu, v, 1);
            if (tid == 0) {
                if (q_out) q_out[0] = v / (float)NPIX;
                g_done2 = 0;
            }
        }
    }
}

// ---------------- launch ----------------
extern "C" void kernel_launch(void* const* d_in, const int* in_sizes, int n_in,
                              void* d_out, int out_size) {
    const float* a = (const float*)d_in[0];
    const float* b = (const float*)d_in[1];
    const float* img;
    const float* bunch;
    if (in_sizes[0] > in_sizes[1]) { bunch = a; img = b; }
    else                           { img = a;  bunch = b; }

    float* out = (float*)d_out;
    float* qdst = nullptr;
    float* patch = nullptr;
    if (out_size >= NPIX + 1)      { qdst = out; patch = out + 1; }
    else if (out_size == NPIX)     { patch = out; }
    else                           { qdst = out; }

    // host-side double-precision gaussian window
    GW gwp;
    {
        double t[WS], s = 0.0;
        double sg = (double)WS / 6.0;
        for (int i = 0; i < WS; i++) {
            double d = (double)(i - RAD);
            t[i] = exp(-(d * d) / (2.0 * sg * sg));
            s += t[i];
        }
        for (int i = 0; i < WS; i++) gwp.w[i] = (float)(t[i] / s);
    }

    static bool attr_set = false;
    if (!attr_set) {
        cudaFuncSetAttribute(mef_stats_k, cudaFuncAttributeMaxDynamicSharedMemorySize, SMEM_TOTAL);
        attr_set = true;
    }

    mef_stats_k<<<dim3(WW / TW, HH / TH), NT2, SMEM_TOTAL>>>(img, bunch, patch, gwp);
    mef_blend_k<<<BLENDB, NT2>>>(qdst);
}

// round 16
// speedup vs baseline: 1.1609x; 1.1609x over previous
#include <cuda_runtime.h>
#include <cuda_fp16.h>
#include <math.h>

// ---------------- problem constants ----------------
#define HH      1024
#define WW      1024
#define NPIX    (HH * WW)
#define KK      8
#define WS      11
#define RAD     5

// ---------------- main tiling: 64 x 32 tiles, 512 threads, 2 blocks/SM ----------------
#define TW       64
#define TH       32
#define HTW      74            // TW + 2*RAD
#define HTH      42            // TH + 2*RAD
#define HT       (HTW * HTH)   // 3108
#define NT2      512
#define NLOAD    7             // ceil(HT / NT2)
#define VBW      75            // vb f01 row stride (float2 units)
#define VBW2     76            // vb f2h row stride (half units)
#define MAINB    512           // stats tiles
#define BLENDB   256           // blend blocks (2 tiles each)

// smem layout (bytes), aligned
#define OFF_F01   0                       // float2[HT]      24864
#define OFF_VB01  24864                   // float2[32*75]   19200
#define OFF_F2    44064                   // half [HT]        6216
#define OFF_VB2   50288                   // half [32*76]     4864
#define SMEM_TOTAL 55152

struct GW { float w[WS]; };

// ---------------- scratch (static device globals; no allocation) ----------------
__device__ uint2 g_muY2[KK * NPIX / 4];   // per-pixel muYs (shifted) as 4 halfs (16MB)
__device__ uint2 g_cs2[NPIX / 4];         // per-pixel cs_map as 4 halfs (2MB)
__device__ uint2 g_mx2[NPIX / 4];         // per-pixel muXs (shifted) as 4 halfs (2MB)
__device__ float g_lY_part[KK * MAINB];
__device__ float g_lG[KK];
__device__ float g_q_part[BLENDB];
__device__ int   g_done1 = 0;
__device__ int   g_done2 = 0;

// ======================= separable blur helpers =======================
// Vertical: 6 consecutive output rows per task, 16 taps -> 2.67 loads/output.
// 444 tasks (6 rowgroups x 74 cols) / 512 threads. Groups 0-4 need no bound check.
__device__ __forceinline__ void vpass6(const float2* __restrict__ f01,
                                       const __half* __restrict__ f2h,
                                       float2* __restrict__ vb01,
                                       __half* __restrict__ vb2h,
                                       const float* gw, int tid) {
    if (tid < 444) {
        int g = tid / HTW, c = tid - g * HTW;
        int r0 = g * 6;
        float ax[6], ay[6], az[6];
#pragma unroll
        for (int i = 0; i < 6; i++) { ax[i] = 0.f; ay[i] = 0.f; az[i] = 0.f; }
        const float2* p01 = f01 + r0 * HTW + c;
        const __half* p2  = f2h + r0 * HTW + c;
        if (r0 + 15 < HTH) {            // rowgroups 0-4: all taps in range
#pragma unroll
            for (int j = 0; j < 16; j++) {
                float2 v = p01[j * HTW];
                float  z = __half2float(p2[j * HTW]);
#pragma unroll
                for (int i = 0; i < 6; i++) {
                    if (i <= j && j - i <= 10) {
                        float gg = gw[j - i];
                        ax[i] += gg * v.x; ay[i] += gg * v.y; az[i] += gg * z;
                    }
                }
            }
        } else {                         // last rowgroup: guard tail taps
#pragma unroll
            for (int j = 0; j < 16; j++) {
                if (r0 + j < HTH) {
                    float2 v = p01[j * HTW];
                    float  z = __half2float(p2[j * HTW]);
#pragma unroll
                    for (int i = 0; i < 6; i++) {
                        if (i <= j && j - i <= 10) {
                            float gg = gw[j - i];
                            ax[i] += gg * v.x; ay[i] += gg * v.y; az[i] += gg * z;
                        }
                    }
                }
            }
        }
#pragma unroll
        for (int i = 0; i < 6; i++) {
            int r = r0 + i;
            if (r < TH) {
                vb01[r * VBW + c] = make_float2(ax[i], ay[i]);
                vb2h[r * VBW2 + c] = __float2half_rn(az[i]);
            }
        }
    }
}

// Horizontal: lane = row (f01 stride conflict-free; f2h benign), 4 cols/thread.
__device__ __forceinline__ void hpass(const float2* __restrict__ vb01,
                                      const __half* __restrict__ vb2h,
                                      const float* gw, int row, int x0, float3* out) {
    float ax[4], ay[4], az[4];
#pragma unroll
    for (int i = 0; i < 4; i++) { ax[i] = 0.f; ay[i] = 0.f; az[i] = 0.f; }
    const float2* p01 = vb01 + row * VBW + x0;
    const __half* p2  = vb2h + row * VBW2 + x0;
#pragma unroll
    for (int j = 0; j < 14; j++) {
        float2 v = p01[j];
        float  z = __half2float(p2[j]);
#pragma unroll
        for (int i = 0; i < 4; i++) {
            if (i <= j && j - i <= 10) {
                float gg = gw[j - i];
                ax[i] += gg * v.x; ay[i] += gg * v.y; az[i] += gg * z;
            }
        }
    }
#pragma unroll
    for (int i = 0; i < 4; i++) out[i] = make_float3(ax[i], ay[i], az[i]);
}

// Pack-write: load bunch k tile (shifted), build (s, s²) fp32 + (s·o') half.
__device__ __forceinline__ void pack_write(const float* __restrict__ bb,
                                           const int* goff, const __half2* h01,
                                           const __half2* h2p,
                                           float2* __restrict__ s_f01,
                                           __half* __restrict__ s_f2h, int tid) {
#pragma unroll
    for (int i = 0; i < NLOAD; i++) {
        int e = tid + i * NT2;
        if (e < HT) {
            int o = goff[i];
            float v0 = -0.5f, v1 = -0.5f, v2 = -0.5f;
            if (o >= 0) {
                v0 = bb[o] - 0.5f; v1 = bb[NPIX + o] - 0.5f; v2 = bb[2 * NPIX + o] - 0.5f;
            }
            float2 o01 = __half22float2(h01[i]);
            float  o2  = __half2float((i & 1) ? __high2half(h2p[i >> 1])
                                              : __low2half(h2p[i >> 1]));
            s_f01[e] = make_float2((v0 + v1 + v2) * (1.f / 3.f),
                                   (v0 * v0 + v1 * v1 + v2 * v2) * (1.f / 3.f));
            s_f2h[e] = __float2half_rn((v0 * o01.x + v1 * o01.y + v2 * o2) * (1.f / 3.f));
        }
    }
}

__device__ __forceinline__ uint2 pack4h(float a, float b, float c, float d) {
    __half2 p0 = __floats2half2_rn(a, b);
    __half2 p1 = __floats2half2_rn(c, d);
    uint2 u;
    u.x = *(const unsigned int*)&p0;
    u.y = *(const unsigned int*)&p1;
    return u;
}

// ======================= k1: stats pass =======================
// Shifted domain v' = v - 0.5 (exact; reference zero-pads raw => padded v' = -0.5).
__global__ __launch_bounds__(NT2, 2) void mef_stats_k(
    const float* __restrict__ img,
    const float* __restrict__ bunch,
    float* __restrict__ patch_out,
    GW gwp)
{
    extern __shared__ char sm[];
    float2* s_f01  = (float2*)(sm + OFF_F01);
    float2* s_vb01 = (float2*)(sm + OFF_VB01);
    __half* s_f2h  = (__half*)(sm + OFF_F2);
    __half* s_vb2h = (__half*)(sm + OFF_VB2);
    __shared__ float s_ly[16 * KK];     // per-warp per-k lY partials
    __shared__ float qw[16];
    const float* gw = gwp.w;

    int tid = threadIdx.x;
    int lane = tid & 31;
    int wid = tid >> 5;
    int row = tid & 31;          // hpass: output row
    int x0c = (tid >> 5) * 4;    // hpass: 4 consecutive output cols
    int bx = blockIdx.x, by = blockIdx.y;
    int T  = by * gridDim.x + bx;    // tile id 0..511
    int gx0 = bx * TW - RAD, gy0 = by * TH - RAD;

    // per-thread halo state: global offsets + output-image channels (half regs)
    int goff[NLOAD];
    __half2 h01[NLOAD];          // (o0', o1')
    __half2 h2p[4];              // o2' packed pairs
#pragma unroll
    for (int i = 0; i < 4; i++) h2p[i] = __halves2half2(__float2half(0.f), __float2half(0.f));

#pragma unroll
    for (int i = 0; i < NLOAD; i++) {
        int e = tid + i * NT2;
        float o0 = -0.5f, o1 = -0.5f, o2 = -0.5f;
        int o = -2;
        if (e < HT) {
            int hy = e / HTW, hx = e - hy * HTW;
            int gy = gy0 + hy, gx = gx0 + hx;
            o = (((unsigned)gy < HH) && ((unsigned)gx < WW)) ? gy * WW + gx : -1;
            if (o >= 0) {
                o0 = img[o] - 0.5f; o1 = img[NPIX + o] - 0.5f; o2 = img[2 * NPIX + o] - 0.5f;
            }
            s_f01[e] = make_float2((o0 + o1 + o2) * (1.f / 3.f),
                                   (o0 * o0 + o1 * o1 + o2 * o2) * (1.f / 3.f));
            s_f2h[e] = __float2half_rn(0.f);
        }
        goff[i] = o;
        h01[i] = __floats2half2_rn(o0, o1);
        __half h2v = __float2half_rn(o2);
        if (i & 1) h2p[i >> 1] = __halves2half2(__low2half(h2p[i >> 1]), h2v);
        else       h2p[i >> 1] = __halves2half2(h2v, __high2half(h2p[i >> 1]));
    }
    __syncthreads();

    vpass6(s_f01, s_f2h, s_vb01, s_vb2h, gw, tid);
    __syncthreads();                 // vb ready; pack free
    float3 xo[4];
    hpass(s_vb01, s_vb2h, gw, row, x0c, xo);
    float muXs[4], sX2[4];
#pragma unroll
    for (int i = 0; i < 4; i++) { muXs[i] = xo[i].x; sX2[i] = xo[i].y - muXs[i] * muXs[i]; }

    // write pack for k=0 while other warps still in hpass (same barrier interval)
    pack_write(bunch, goff, h01, h2p, s_f01, s_f2h, tid);
    __syncthreads();                 // pack(0) ready; vb consumed

    float best[4], bestXY[4];
    int pidx[4];
#pragma unroll
    for (int i = 0; i < 4; i++) { best[i] = -1e30f; bestXY[i] = 0.f; pidx[i] = 0; }

    for (int k = 0; k < KK; k++) {
        vpass6(s_f01, s_f2h, s_vb01, s_vb2h, gw, tid);
        __syncthreads();             // vb ready; pack free
        float3 yo[4];
        hpass(s_vb01, s_vb2h, gw, row, x0c, yo);

#pragma unroll
        for (int i = 0; i < 4; i++) {
            float muYs = yo[i].x;
            float sY2 = yo[i].y - muYs * muYs;
            float sXY = yo[i].z - muXs[i] * muYs;
            if (sY2 > best[i]) { best[i] = sY2; bestXY[i] = sXY; pidx[i] = k; }
        }
        // store muYs for blend pass (half, tile-private coalesced layout)
        g_muY2[(size_t)(T * KK + k) * NT2 + tid] =
            pack4h(yo[0].x, yo[1].x, yo[2].x, yo[3].x);
        // per-warp lY partial (exact: tiles partition image)
        float lsum = yo[0].x + yo[1].x + yo[2].x + yo[3].x;
#pragma unroll
        for (int o = 16; o > 0; o >>= 1) lsum += __shfl_xor_sync(0xffffffffu, lsum, o);
        if (lane == 0) s_ly[wid * KK + k] = lsum;

        // prefetch + pack next exposure, overlapping hpass/stat issue stream
        if (k < KK - 1)
            pack_write(bunch + (size_t)(3 * (k + 1)) * NPIX, goff, h01, h2p,
                       s_f01, s_f2h, tid);
        __syncthreads();             // pack(k+1) ready; vb consumed; s_ly visible
    }

    // ---- epilogue ----
    // lY partials: fold 16 warps per k (8 threads, deterministic serial order)
    if (tid < KK) {
        float v = 0.f;
#pragma unroll
        for (int w = 0; w < 16; w++) v += s_ly[w * KK + tid];
        g_lY_part[tid * MAINB + T] = v;
    }

    // cs + muXs (half) and patch staging; cs via approx div (feeds half storage)
    float* sidx = (float*)s_vb01;   // staging: 2048 floats
    float csv[4];
#pragma unroll
    for (int i = 0; i < 4; i++) {
        csv[i] = __fdividef(2.f * bestXY[i] + 9e-4f,
                            fmaxf(sX2[i] + best[i] + 9e-4f, 1e-6f));   // C2 = 0.03^2
        sidx[row * 64 + x0c + i] = (float)pidx[i];
    }
    g_cs2[(size_t)T * NT2 + tid] = pack4h(csv[0], csv[1], csv[2], csv[3]);
    g_mx2[(size_t)T * NT2 + tid] = pack4h(muXs[0], muXs[1], muXs[2], muXs[3]);

    __syncthreads();
    if (patch_out) {
        // scalar stores: patch_out base is only 4B-aligned (out + 1).
        int px = tid * 4;
        int rr = px >> 6, cc = px & 63;
        float* dst = &patch_out[(by * TH + rr) * WW + bx * TW + cc];
        const float* src = &sidx[px];
        dst[0] = src[0]; dst[1] = src[1]; dst[2] = src[2]; dst[3] = src[3];
    }

    // ---- last block: fold lY partials -> lG ----
    __shared__ int isLast;
    if (tid == 0) {
        __threadfence();
        isLast = (atomicAdd(&g_done1, 1) == MAINB - 1);
    }
    __syncthreads();
    if (isLast) {
        __threadfence();
        for (int k = 0; k < KK; k++) {
            float s = g_lY_part[k * MAINB + tid];     // MAINB == NT2 == 512
#pragma unroll
            for (int o = 16; o > 0; o >>= 1) s += __shfl_xor_sync(0xffffffffu, s, o);
            if (lane == 0) qw[wid] = s;
            __syncthreads();
            if (tid < 16) {
                float v = qw[tid];
                v += __shfl_xor_sync(0x0000ffffu, v, 8);
                v += __shfl_xor_sync(0x0000ffffu, v, 4);
                v += __shfl_xor_sync(0x0000ffffu, v, 2);
                v += __shfl_xor_sync(0x0000ffffu, v, 1);
                if (tid == 0) {
                    double d = (double)v / (double)NPIX;   // = mean(muYs) = lY - 0.5
                    g_lG[k] = (float)exp(-(d * d) / 0.08); // DENOM_G = 2*0.2^2
                }
            }
            __syncthreads();
        }
        if (tid == 0) g_done1 = 0;   // self-reset for next graph replay
    }
}

// ======================= k2: luminance blend + q (2 tiles/block, 8 px/thread) =======================
__global__ __launch_bounds__(NT2) void mef_blend_k(float* __restrict__ q_out) {
    __shared__ float s_lG[KK];
    __shared__ float qw[16];
    int tid = threadIdx.x;
    int lane = tid & 31, wid = tid >> 5;
    int T  = blockIdx.x * 2 + (tid >> 8);
    int tp = tid & 255;               // uint4 index within tile

    if (tid < KK) s_lG[tid] = g_lG[tid];
    __syncthreads();

    const uint4* muY4 = (const uint4*)g_muY2;
    const uint4* cs4  = (const uint4*)g_cs2;
    const uint4* mx4  = (const uint4*)g_mx2;

    float num[8], den[8];
#pragma unroll
    for (int i = 0; i < 8; i++) { num[i] = 0.f; den[i] = 0.f; }

#pragma unroll
    for (int k = 0; k < KK; k++) {
        uint4 u = muY4[(size_t)(T * KK + k) * 256 + tp];
        float2 f0 = __half22float2(*(const __half2*)&u.x);
        float2 f1 = __half22float2(*(const __half2*)&u.y);
        float2 f2 = __half22float2(*(const __half2*)&u.z);
        float2 f3 = __half22float2(*(const __half2*)&u.w);
        float m[8] = {f0.x, f0.y, f1.x, f1.y, f2.x, f2.y, f3.x, f3.y};
        float lGk = s_lG[k];
#pragma unroll
        for (int i = 0; i < 8; i++) {
            float wgt = lGk * __expf(-(m[i] * m[i]) * (1.f / 0.08f));   // DENOM_L
            num[i] += wgt * (m[i] + 0.5f);
            den[i] += wgt;
        }
    }

    uint4 cu = cs4[(size_t)T * 256 + tp];
    uint4 mu = mx4[(size_t)T * 256 + tp];
    float cs[8], mx[8];
    {
        float2 a0 = __half22float2(*(const __half2*)&cu.x);
        float2 a1 = __half22float2(*(const __half2*)&cu.y);
        float2 a2 = __half22float2(*(const __half2*)&cu.z);
        float2 a3 = __half22float2(*(const __half2*)&cu.w);
        cs[0]=a0.x; cs[1]=a0.y; cs[2]=a1.x; cs[3]=a1.y;
        cs[4]=a2.x; cs[5]=a2.y; cs[6]=a3.x; cs[7]=a3.y;
        float2 b0 = __half22float2(*(const __half2*)&mu.x);
        float2 b1 = __half22float2(*(const __half2*)&mu.y);
        float2 b2 = __half22float2(*(const __half2*)&mu.z);
        float2 b3 = __half22float2(*(const __half2*)&mu.w);
        mx[0]=b0.x; mx[1]=b0.y; mx[2]=b1.x; mx[3]=b1.y;
        mx[4]=b2.x; mx[5]=b2.y; mx[6]=b3.x; mx[7]=b3.y;
    }

    float qsum = 0.f;
#pragma unroll
    for (int i = 0; i < 8; i++) {
        float muX  = mx[i] + 0.5f;
        float muYb = __fdividef(num[i], den[i]);
        float l = __fdividef(2.f * muX * muYb + 1e-4f,
                             fmaxf(muX * muX + muYb * muYb + 1e-4f, 1e-6f));  // C1
        qsum += l * cs[i];
    }

#pragma unroll
    for (int o = 16; o > 0; o >>= 1) qsum += __shfl_xor_sync(0xffffffffu, qsum, o);
    if (lane == 0) qw[wid] = qsum;
    __syncthreads();
    if (tid < 16) {
        float v = qw[tid];
        v += __shfl_xor_sync(0x0000ffffu, v, 8);
        v += __shfl_xor_sync(0x0000ffffu, v, 4);
        v += __shfl_xor_sync(0x0000ffffu, v, 2);
        v += __shfl_xor_sync(0x0000ffffu, v, 1);
        if (tid == 0) g_q_part[blockIdx.x] = v;
    }

    __shared__ int isLast;
    if (tid == 0) {
        __threadfence();
        isLast = (atomicAdd(&g_done2, 1) == BLENDB - 1);
    }
    __syncthreads();
    if (isLast) {
        __threadfence();
        float s = (tid < BLENDB) ? g_q_part[tid] : 0.f;
#pragma unroll
        for (int o = 16; o > 0; o >>= 1) s += __shfl_xor_sync(0xffffffffu, s, o);
        if (lane == 0) qw[wid] = s;
        __syncthreads();
        if (tid < 16) {
            float v = qw[tid];
            v += __shfl_xor_sync(0x0000ffffu, v, 8);
            v += __shfl_xor_sync(0x0000ffffu, v, 4);
            v += __shfl_xor_sync(0x0000ffffu, v, 2);
            v += __shfl_xor_sync(0x0000ffffu, v, 1);
            if (tid == 0) {
                if (q_out) q_out[0] = v / (float)NPIX;
                g_done2 = 0;
            }
        }
    }
}

// ---------------- launch ----------------
extern "C" void kernel_launch(void* const* d_in, const int* in_sizes, int n_in,
                              void* d_out, int out_size) {
    const float* a = (const float*)d_in[0];
    const float* b = (const float*)d_in[1];
    const float* img;
    const float* bunch;
    if (in_sizes[0] > in_sizes[1]) { bunch = a; img = b; }
    else                           { img = a;  bunch = b; }

    float* out = (float*)d_out;
    float* qdst = nullptr;
    float* patch = nullptr;
    if (out_size >= NPIX + 1)      { qdst = out; patch = out + 1; }
    else if (out_size == NPIX)     { patch = out; }
    else                           { qdst = out; }

    // host-side double-precision gaussian window
    GW gwp;
    {
        double t[WS], s = 0.0;
        double sg = (double)WS / 6.0;
        for (int i = 0; i < WS; i++) {
            double d = (double)(i - RAD);
            t[i] = exp(-(d * d) / (2.0 * sg * sg));
            s += t[i];
        }
        for (int i = 0; i < WS; i++) gwp.w[i] = (float)(t[i] / s);
    }

    static bool attr_set = false;
    if (!attr_set) {
        cudaFuncSetAttribute(mef_stats_k, cudaFuncAttributeMaxDynamicSharedMemorySize, SMEM_TOTAL);
        attr_set = true;
    }

    mef_stats_k<<<dim3(WW / TW, HH / TH), NT2, SMEM_TOTAL>>>(img, bunch, patch, gwp);
    mef_blend_k<<<BLENDB, NT2>>>(qdst);
}